// round 4
// baseline (speedup 1.0000x reference)
#include <cuda_runtime.h>
#include <cstdint>

#define B_ 8
#define S_ 2048
#define D_ 1024
#define DS_ 128
#define MROWS (B_*S_)   // 16384

// ---------------- scratch (static device globals; no allocation) -------------
__device__ float g_k[MROWS*DS_];
__device__ float g_v[MROWS*DS_];
__device__ float g_q[MROWS*DS_];
__device__ float g_a[MROWS*DS_];
__device__ float g_y[MROWS*DS_];

// ---------------- packed fp32x2 helpers (FFMA2 path) -------------------------
typedef unsigned long long u64;

__device__ __forceinline__ u64 pk2(float lo, float hi) {
    u64 r; asm("mov.b64 %0,{%1,%2};" : "=l"(r) : "f"(lo), "f"(hi)); return r;
}
__device__ __forceinline__ float2 up2(u64 v) {
    float2 r; asm("mov.b64 {%0,%1}, %2;" : "=f"(r.x), "=f"(r.y) : "l"(v)); return r;
}
__device__ __forceinline__ u64 ffma2(u64 a, u64 b, u64 c) {
    u64 d; asm("fma.rn.f32x2 %0,%1,%2,%3;" : "=l"(d) : "l"(a), "l"(b), "l"(c)); return d;
}
__device__ __forceinline__ u64 fmul2(u64 a, u64 b) {
    u64 d; asm("mul.rn.f32x2 %0,%1,%2;" : "=l"(d) : "l"(a), "l"(b)); return d;
}
__device__ __forceinline__ u64 fadd2(u64 a, u64 b) {
    u64 d; asm("add.rn.f32x2 %0,%1,%2;" : "=l"(d) : "l"(a), "l"(b)); return d;
}

// =============================================================================
// Kernel 1: input projections. O = X @ W^T with per-variant epilogue.
//   blockIdx.y: 0 -> k (l2norm), 1 -> q (l2norm), 2 -> v (none), 3 -> alpha
// Tile: BM=64, BN=128(full), BK=16, 256 threads, micro-tile 8x4, packed FFMA2.
// =============================================================================
__global__ __launch_bounds__(256) void proj_kernel(
    const float* __restrict__ x,
    const float* __restrict__ Wk, const float* __restrict__ Wv,
    const float* __restrict__ Wq, const float* __restrict__ Waw,
    const float* __restrict__ Wab, const float* __restrict__ lam)
{
    const int which = blockIdx.y;
    const float* W; float* O; int epi;
    if (which == 0)      { W = Wk;  O = g_k; epi = 1; }
    else if (which == 1) { W = Wq;  O = g_q; epi = 1; }
    else if (which == 2) { W = Wv;  O = g_v; epi = 0; }
    else                 { W = Waw; O = g_a; epi = 2; }

    __shared__ __align__(16) float sX[16][68];
    __shared__ __align__(16) float sW[16][132];

    const int tid = threadIdx.x;
    const int tx  = tid & 31;   // 32 col-groups
    const int ty  = tid >> 5;   // 8 row-groups
    const int m0  = blockIdx.x * 64;

    u64 acc2[8][2];
#pragma unroll
    for (int i = 0; i < 8; i++) { acc2[i][0] = 0ULL; acc2[i][1] = 0ULL; }

    const int lxr = tid >> 2;          // x-load: row within tile
    const int lxk = (tid & 3) * 4;     // x-load: k offset

    for (int kc = 0; kc < D_; kc += 16) {
        float4 xv = *(const float4*)&x[(size_t)(m0 + lxr) * D_ + kc + lxk];
        int n0a = tid >> 2, k0a = (tid & 3) * 4;
        float4 wv0 = *(const float4*)&W[(size_t)n0a * D_ + kc + k0a];
        int idx2 = tid + 256;
        int n0b = idx2 >> 2, k0b = (idx2 & 3) * 4;
        float4 wv1 = *(const float4*)&W[(size_t)n0b * D_ + kc + k0b];

        __syncthreads();
        sX[lxk + 0][lxr] = xv.x; sX[lxk + 1][lxr] = xv.y;
        sX[lxk + 2][lxr] = xv.z; sX[lxk + 3][lxr] = xv.w;
        sW[k0a + 0][n0a] = wv0.x; sW[k0a + 1][n0a] = wv0.y;
        sW[k0a + 2][n0a] = wv0.z; sW[k0a + 3][n0a] = wv0.w;
        sW[k0b + 0][n0b] = wv1.x; sW[k0b + 1][n0b] = wv1.y;
        sW[k0b + 2][n0b] = wv1.z; sW[k0b + 3][n0b] = wv1.w;
        __syncthreads();

#pragma unroll
        for (int k = 0; k < 16; k++) {
            ulonglong2 b4 = *(const ulonglong2*)&sW[k][tx * 4];
            float a_[8];
#pragma unroll
            for (int i = 0; i < 8; i++) a_[i] = sX[k][ty * 8 + i];
#pragma unroll
            for (int i = 0; i < 8; i++) {
                u64 a2 = pk2(a_[i], a_[i]);
                acc2[i][0] = ffma2(a2, b4.x, acc2[i][0]);
                acc2[i][1] = ffma2(a2, b4.y, acc2[i][1]);
            }
        }
    }

    float acc[8][4];
#pragma unroll
    for (int i = 0; i < 8; i++) {
        float2 lo = up2(acc2[i][0]);
        float2 hi = up2(acc2[i][1]);
        acc[i][0] = lo.x; acc[i][1] = lo.y; acc[i][2] = hi.x; acc[i][3] = hi.y;
    }

    const int nbase = tx * 4;
    if (epi == 0) {
#pragma unroll
        for (int i = 0; i < 8; i++) {
            float4 o = make_float4(acc[i][0], acc[i][1], acc[i][2], acc[i][3]);
            *(float4*)&O[(size_t)(m0 + ty * 8 + i) * DS_ + nbase] = o;
        }
    } else if (epi == 1) {
#pragma unroll
        for (int i = 0; i < 8; i++) {
            float ss = acc[i][0] * acc[i][0] + acc[i][1] * acc[i][1]
                     + acc[i][2] * acc[i][2] + acc[i][3] * acc[i][3];
#pragma unroll
            for (int off = 16; off; off >>= 1)
                ss += __shfl_xor_sync(0xffffffffu, ss, off);
            float inv = 1.f / fmaxf(sqrtf(ss), 1e-12f);
            float4 o = make_float4(acc[i][0] * inv, acc[i][1] * inv,
                                   acc[i][2] * inv, acc[i][3] * inv);
            *(float4*)&O[(size_t)(m0 + ty * 8 + i) * DS_ + nbase] = o;
        }
    } else {
        float bias[4], loga[4];
#pragma unroll
        for (int j = 0; j < 4; j++) {
            int n = nbase + j;
            bias[j] = Wab[n];
            float sl = 1.f / (1.f + __expf(-lam[n]));
            loga[j] = __logf(sl + 1e-8f);
        }
#pragma unroll
        for (int i = 0; i < 8; i++) {
            float4 o;
            float r0 = 1.f / (1.f + __expf(-(acc[i][0] + bias[0])));
            float r1 = 1.f / (1.f + __expf(-(acc[i][1] + bias[1])));
            float r2 = 1.f / (1.f + __expf(-(acc[i][2] + bias[2])));
            float r3 = 1.f / (1.f + __expf(-(acc[i][3] + bias[3])));
            o.x = __expf(8.f * r0 * loga[0]);
            o.y = __expf(8.f * r1 * loga[1]);
            o.z = __expf(8.f * r2 * loga[2]);
            o.w = __expf(8.f * r3 * loga[3]);
            *(float4*)&O[(size_t)(m0 + ty * 8 + i) * DS_ + nbase] = o;
        }
    }
}

// =============================================================================
// Kernel 2: sequential gated-delta recurrence.
// 256 threads per CTA (one CTA per batch). Thread pair (2c,2c+1) owns column c:
// even thread rows [0,64), odd thread rows [64,128), as 32 packed fp32-pairs.
// Single __syncthreads per step; q and sc0 cached in registers so no smem is
// read after the barrier (prefetch of the next step writes the other buffer
// before the barrier).
// =============================================================================
__global__ __launch_bounds__(256, 1) void recurrence_kernel()
{
    const int b   = blockIdx.x;
    const int tid = threadIdx.x;
    const int col = tid >> 1;
    const int half = tid & 1;
    const int lj  = tid & 127;
    const bool loader_ka = (tid < 128);

    __shared__ __align__(16) float sk[2][DS_];
    __shared__ __align__(16) float sv[2][DS_];
    __shared__ __align__(16) float sq[2][DS_];
    __shared__ __align__(16) float sa[2][DS_];
    __shared__ __align__(16) float sc0[2][DS_];
    __shared__ float red[2][8];

    u64 h[32];
#pragma unroll
    for (int j = 0; j < 32; j++) h[j] = 0ULL;

    const float* bk = g_k + (size_t)b * S_ * DS_;
    const float* bv = g_v + (size_t)b * S_ * DS_;
    const float* bq = g_q + (size_t)b * S_ * DS_;
    const float* ba = g_a + (size_t)b * S_ * DS_;
    float*       by = g_y + (size_t)b * S_ * DS_;

    // fill buffer 0
    if (loader_ka) {
        float kk = bk[lj], aa = ba[lj];
        sk[0][lj] = kk; sa[0][lj] = aa; sc0[0][lj] = (1.f - aa) * kk;
    } else {
        sq[0][lj] = bq[lj]; sv[0][lj] = bv[lj];
    }
    __syncthreads();

    int buf = 0;
    for (int step = 0; step < S_; ++step) {
        const int nb = buf ^ 1;

        // prefetch next step (global loads issued early), and this step's v
        // (LDS latency overlaps the matvec loop below)
        float p0 = 0.f, p1 = 0.f;
        if (step + 1 < S_) {
            size_t o = (size_t)(step + 1) * DS_ + lj;
            if (loader_ka) { p0 = bk[o]; p1 = ba[o]; }
            else           { p0 = bq[o]; p1 = bv[o]; }
        }
        float myv = sv[buf][col];

        // ---- matvecs over this thread's half-column: pred_h = q.h, kp_h = k.h
        const ulonglong2* q4 = (const ulonglong2*)&sq[buf][half * 64];
        const ulonglong2* k4 = (const ulonglong2*)&sk[buf][half * 64];
        u64 q_r[32];
        u64 p2a = 0, p2b = 0, kp2a = 0, kp2b = 0;
#pragma unroll
        for (int jj = 0; jj < 16; jj++) {
            ulonglong2 qA = q4[jj];
            ulonglong2 kA = k4[jj];
            q_r[2 * jj]     = qA.x;
            q_r[2 * jj + 1] = qA.y;
            p2a  = ffma2(qA.x, h[2 * jj],     p2a);
            kp2a = ffma2(kA.x, h[2 * jj],     kp2a);
            p2b  = ffma2(qA.y, h[2 * jj + 1], p2b);
            kp2b = ffma2(kA.y, h[2 * jj + 1], kp2b);
        }
        float2 pp = up2(fadd2(p2a, p2b));
        float pred_h = pp.x + pp.y;
        float2 kk2 = up2(fadd2(kp2a, kp2b));
        float kp_h = kk2.x + kk2.y;

        // combine half-column partials within the lane pair
        float pred = pred_h + __shfl_xor_sync(0xffffffffu, pred_h, 1);
        float kp   = kp_h   + __shfl_xor_sync(0xffffffffu, kp_h,   1);

        float dv  = myv - kp;
        float e   = myv - pred;
        e = (half == 0) ? e * e : 0.f;

        // ---- decay h *= a, cache sc0 in regs (issues under the shfl chain) --
        const ulonglong2* a4 = (const ulonglong2*)&sa[buf][half * 64];
        const ulonglong2* c4 = (const ulonglong2*)&sc0[buf][half * 64];
        u64 c_r[32];
#pragma unroll
        for (int jj = 0; jj < 16; jj++) {
            ulonglong2 aA = a4[jj];
            ulonglong2 cA = c4[jj];
            c_r[2 * jj]     = cA.x;
            c_r[2 * jj + 1] = cA.y;
            h[2 * jj]     = fmul2(aA.x, h[2 * jj]);
            h[2 * jj + 1] = fmul2(aA.y, h[2 * jj + 1]);
        }

        // ---- err reduction to per-warp partials --------------------------
#pragma unroll
        for (int off = 16; off; off >>= 1)
            e += __shfl_xor_sync(0xffffffffu, e, off);
        if ((tid & 31) == 0) red[buf][tid >> 5] = e;

        // stash prefetched step into the other buffer (pre-barrier)
        if (step + 1 < S_) {
            if (loader_ka) {
                sk[nb][lj] = p0; sa[nb][lj] = p1; sc0[nb][lj] = (1.f - p1) * p0;
            } else {
                sq[nb][lj] = p0; sv[nb][lj] = p1;
            }
        }
        __syncthreads();   // the ONLY barrier per step

        float err = ((red[buf][0] + red[buf][1]) + (red[buf][2] + red[buf][3]))
                  + ((red[buf][4] + red[buf][5]) + (red[buf][6] + red[buf][7]));
        float sur = 1.f / (1.f + __expf(-err * (1.f / 1.000001f)));
        float sdv = sur * dv;
        u64 sdv2 = pk2(sdv, sdv);

        // ---- finish H update and y = q . H_new (all operands in registers) -
        u64 y2a = 0, y2b = 0;
#pragma unroll
        for (int jj = 0; jj < 16; jj++) {
            h[2 * jj] = ffma2(c_r[2 * jj], sdv2, h[2 * jj]);
            y2a = ffma2(q_r[2 * jj], h[2 * jj], y2a);
            h[2 * jj + 1] = ffma2(c_r[2 * jj + 1], sdv2, h[2 * jj + 1]);
            y2b = ffma2(q_r[2 * jj + 1], h[2 * jj + 1], y2b);
        }
        float2 yy = up2(fadd2(y2a, y2b));
        float yh = yy.x + yy.y;
        float yf = yh + __shfl_xor_sync(0xffffffffu, yh, 1);
        if (half == 0) by[(size_t)step * DS_ + col] = yf;

        buf = nb;
    }
}

// =============================================================================
// Kernel 3: fused RMSNorm(y) * norm_weight, then @ W_o^T. Packed FFMA2.
// =============================================================================
__global__ __launch_bounds__(256) void out_kernel(
    const float* __restrict__ Wo, const float* __restrict__ nw,
    float* __restrict__ out)
{
    __shared__ __align__(16) float sY[128][68];   // [k][m]
    __shared__ __align__(16) float sW[16][132];   // [k][n]
    __shared__ float sScale[64];
    __shared__ float snw[128];

    const int tid = threadIdx.x;
    const int tx = tid & 31, ty = tid >> 5;
    const int m0 = blockIdx.x * 64, n0 = blockIdx.y * 128;

    if (tid < 128) snw[tid] = nw[tid];

#pragma unroll
    for (int it = 0; it < 8; it++) {
        int idx = tid + it * 256;
        int row = idx >> 5;
        int k4  = (idx & 31) * 4;
        float4 v = *(const float4*)&g_y[(size_t)(m0 + row) * DS_ + k4];
        sY[k4 + 0][row] = v.x; sY[k4 + 1][row] = v.y;
        sY[k4 + 2][row] = v.z; sY[k4 + 3][row] = v.w;
    }
    __syncthreads();

    {
        int row = tid >> 2, part = tid & 3;
        float ss = 0.f;
#pragma unroll
        for (int kkk = 0; kkk < 32; kkk++) {
            float v = sY[part * 32 + kkk][row];
            ss = fmaf(v, v, ss);
        }
        ss += __shfl_xor_sync(0xffffffffu, ss, 1);
        ss += __shfl_xor_sync(0xffffffffu, ss, 2);
        if (part == 0) sScale[row] = rsqrtf(ss * (1.f / 128.f) + 1e-6f);
    }
    __syncthreads();

    for (int idx = tid; idx < 128 * 64; idx += 256) {
        int k = idx >> 6, m = idx & 63;
        sY[k][m] *= sScale[m];
    }

    u64 acc2[8][2];
#pragma unroll
    for (int i = 0; i < 8; i++) { acc2[i][0] = 0ULL; acc2[i][1] = 0ULL; }

    for (int kc = 0; kc < DS_; kc += 16) {
        int n0a = tid >> 2, k0a = (tid & 3) * 4;
        float4 w0 = *(const float4*)&Wo[(size_t)(n0 + n0a) * DS_ + kc + k0a];
        int idx2 = tid + 256;
        int n0b = idx2 >> 2, k0b = (idx2 & 3) * 4;
        float4 w1 = *(const float4*)&Wo[(size_t)(n0 + n0b) * DS_ + kc + k0b];

        __syncthreads();
        sW[k0a + 0][n0a] = w0.x * snw[kc + k0a + 0];
        sW[k0a + 1][n0a] = w0.y * snw[kc + k0a + 1];
        sW[k0a + 2][n0a] = w0.z * snw[kc + k0a + 2];
        sW[k0a + 3][n0a] = w0.w * snw[kc + k0a + 3];
        sW[k0b + 0][n0b] = w1.x * snw[kc + k0b + 0];
        sW[k0b + 1][n0b] = w1.y * snw[kc + k0b + 1];
        sW[k0b + 2][n0b] = w1.z * snw[kc + k0b + 2];
        sW[k0b + 3][n0b] = w1.w * snw[kc + k0b + 3];
        __syncthreads();

#pragma unroll
        for (int k = 0; k < 16; k++) {
            ulonglong2 b4 = *(const ulonglong2*)&sW[k][tx * 4];
            float a_[8];
#pragma unroll
            for (int i = 0; i < 8; i++) a_[i] = sY[kc + k][ty * 8 + i];
#pragma unroll
            for (int i = 0; i < 8; i++) {
                u64 a2 = pk2(a_[i], a_[i]);
                acc2[i][0] = ffma2(a2, b4.x, acc2[i][0]);
                acc2[i][1] = ffma2(a2, b4.y, acc2[i][1]);
            }
        }
    }

#pragma unroll
    for (int i = 0; i < 8; i++) {
        float2 lo = up2(acc2[i][0]);
        float2 hi = up2(acc2[i][1]);
        float4 o = make_float4(lo.x, lo.y, hi.x, hi.y);
        *(float4*)&out[(size_t)(m0 + ty * 8 + i) * D_ + n0 + tx * 4] = o;
    }
}

// =============================================================================
extern "C" void kernel_launch(void* const* d_in, const int* in_sizes, int n_in,
                              void* d_out, int out_size)
{
    const float* x   = (const float*)d_in[0];
    const float* Wk  = (const float*)d_in[1];
    const float* Wv  = (const float*)d_in[2];
    const float* Wq  = (const float*)d_in[3];
    const float* Waw = (const float*)d_in[4];
    const float* Wab = (const float*)d_in[5];
    const float* lam = (const float*)d_in[6];
    const float* Wo  = (const float*)d_in[7];
    const float* nw  = (const float*)d_in[8];
    float* out = (float*)d_out;

    dim3 g1(MROWS / 64, 4);
    proj_kernel<<<g1, 256>>>(x, Wk, Wv, Wq, Waw, Wab, lam);

    recurrence_kernel<<<B_, 256>>>();

    dim3 g3(MROWS / 64, D_ / 128);
    out_kernel<<<g3, 256>>>(Wo, nw, out);
}

// round 8
// speedup vs baseline: 1.0007x; 1.0007x over previous
#include <cuda_runtime.h>
#include <cstdint>

#define B_ 8
#define S_ 2048
#define D_ 1024
#define DS_ 128
#define MROWS (B_*S_)   // 16384

// ---------------- scratch (static device globals; no allocation) -------------
__device__ float g_k[MROWS*DS_];
__device__ float g_v[MROWS*DS_];
__device__ float g_q[MROWS*DS_];
__device__ float g_a[MROWS*DS_];
__device__ float g_y0[MROWS*DS_];   // y partial, rows [0,64)
__device__ float g_y1[MROWS*DS_];   // y partial, rows [64,128)

// ---------------- packed fp32x2 helpers (FFMA2 path) -------------------------
typedef unsigned long long u64;

__device__ __forceinline__ u64 pk2(float lo, float hi) {
    u64 r; asm("mov.b64 %0,{%1,%2};" : "=l"(r) : "f"(lo), "f"(hi)); return r;
}
__device__ __forceinline__ float2 up2(u64 v) {
    float2 r; asm("mov.b64 {%0,%1}, %2;" : "=f"(r.x), "=f"(r.y) : "l"(v)); return r;
}
__device__ __forceinline__ u64 ffma2(u64 a, u64 b, u64 c) {
    u64 d; asm("fma.rn.f32x2 %0,%1,%2,%3;" : "=l"(d) : "l"(a), "l"(b), "l"(c)); return d;
}
__device__ __forceinline__ u64 fmul2(u64 a, u64 b) {
    u64 d; asm("mul.rn.f32x2 %0,%1,%2;" : "=l"(d) : "l"(a), "l"(b)); return d;
}
__device__ __forceinline__ u64 fadd2(u64 a, u64 b) {
    u64 d; asm("add.rn.f32x2 %0,%1,%2;" : "=l"(d) : "l"(a), "l"(b)); return d;
}

// =============================================================================
// Kernel 1: input projections. O = X @ W^T with per-variant epilogue.
//   blockIdx.y: 0 -> k (l2norm), 1 -> q (l2norm), 2 -> v (none), 3 -> alpha
// Tile: BM=64, BN=128(full), BK=16, 256 threads, micro-tile 8x4, packed FFMA2.
// =============================================================================
__global__ __launch_bounds__(256) void proj_kernel(
    const float* __restrict__ x,
    const float* __restrict__ Wk, const float* __restrict__ Wv,
    const float* __restrict__ Wq, const float* __restrict__ Waw,
    const float* __restrict__ Wab, const float* __restrict__ lam)
{
    const int which = blockIdx.y;
    const float* W; float* O; int epi;
    if (which == 0)      { W = Wk;  O = g_k; epi = 1; }
    else if (which == 1) { W = Wq;  O = g_q; epi = 1; }
    else if (which == 2) { W = Wv;  O = g_v; epi = 0; }
    else                 { W = Waw; O = g_a; epi = 2; }

    __shared__ __align__(16) float sX[16][68];
    __shared__ __align__(16) float sW[16][132];

    const int tid = threadIdx.x;
    const int tx  = tid & 31;   // 32 col-groups
    const int ty  = tid >> 5;   // 8 row-groups
    const int m0  = blockIdx.x * 64;

    u64 acc2[8][2];
#pragma unroll
    for (int i = 0; i < 8; i++) { acc2[i][0] = 0ULL; acc2[i][1] = 0ULL; }

    const int lxr = tid >> 2;          // x-load: row within tile
    const int lxk = (tid & 3) * 4;     // x-load: k offset

    for (int kc = 0; kc < D_; kc += 16) {
        float4 xv = *(const float4*)&x[(size_t)(m0 + lxr) * D_ + kc + lxk];
        int n0a = tid >> 2, k0a = (tid & 3) * 4;
        float4 wv0 = *(const float4*)&W[(size_t)n0a * D_ + kc + k0a];
        int idx2 = tid + 256;
        int n0b = idx2 >> 2, k0b = (idx2 & 3) * 4;
        float4 wv1 = *(const float4*)&W[(size_t)n0b * D_ + kc + k0b];

        __syncthreads();
        sX[lxk + 0][lxr] = xv.x; sX[lxk + 1][lxr] = xv.y;
        sX[lxk + 2][lxr] = xv.z; sX[lxk + 3][lxr] = xv.w;
        sW[k0a + 0][n0a] = wv0.x; sW[k0a + 1][n0a] = wv0.y;
        sW[k0a + 2][n0a] = wv0.z; sW[k0a + 3][n0a] = wv0.w;
        sW[k0b + 0][n0b] = wv1.x; sW[k0b + 1][n0b] = wv1.y;
        sW[k0b + 2][n0b] = wv1.z; sW[k0b + 3][n0b] = wv1.w;
        __syncthreads();

#pragma unroll
        for (int k = 0; k < 16; k++) {
            ulonglong2 b4 = *(const ulonglong2*)&sW[k][tx * 4];
            float a_[8];
#pragma unroll
            for (int i = 0; i < 8; i++) a_[i] = sX[k][ty * 8 + i];
#pragma unroll
            for (int i = 0; i < 8; i++) {
                u64 a2 = pk2(a_[i], a_[i]);
                acc2[i][0] = ffma2(a2, b4.x, acc2[i][0]);
                acc2[i][1] = ffma2(a2, b4.y, acc2[i][1]);
            }
        }
    }

    float acc[8][4];
#pragma unroll
    for (int i = 0; i < 8; i++) {
        float2 lo = up2(acc2[i][0]);
        float2 hi = up2(acc2[i][1]);
        acc[i][0] = lo.x; acc[i][1] = lo.y; acc[i][2] = hi.x; acc[i][3] = hi.y;
    }

    const int nbase = tx * 4;
    if (epi == 0) {
#pragma unroll
        for (int i = 0; i < 8; i++) {
            float4 o = make_float4(acc[i][0], acc[i][1], acc[i][2], acc[i][3]);
            *(float4*)&O[(size_t)(m0 + ty * 8 + i) * DS_ + nbase] = o;
        }
    } else if (epi == 1) {
#pragma unroll
        for (int i = 0; i < 8; i++) {
            float ss = acc[i][0] * acc[i][0] + acc[i][1] * acc[i][1]
                     + acc[i][2] * acc[i][2] + acc[i][3] * acc[i][3];
#pragma unroll
            for (int off = 16; off; off >>= 1)
                ss += __shfl_xor_sync(0xffffffffu, ss, off);
            float inv = 1.f / fmaxf(sqrtf(ss), 1e-12f);
            float4 o = make_float4(acc[i][0] * inv, acc[i][1] * inv,
                                   acc[i][2] * inv, acc[i][3] * inv);
            *(float4*)&O[(size_t)(m0 + ty * 8 + i) * DS_ + nbase] = o;
        }
    } else {
        float bias[4], loga[4];
#pragma unroll
        for (int j = 0; j < 4; j++) {
            int n = nbase + j;
            bias[j] = Wab[n];
            float sl = 1.f / (1.f + __expf(-lam[n]));
            loga[j] = __logf(sl + 1e-8f);
        }
#pragma unroll
        for (int i = 0; i < 8; i++) {
            float4 o;
            float r0 = 1.f / (1.f + __expf(-(acc[i][0] + bias[0])));
            float r1 = 1.f / (1.f + __expf(-(acc[i][1] + bias[1])));
            float r2 = 1.f / (1.f + __expf(-(acc[i][2] + bias[2])));
            float r3 = 1.f / (1.f + __expf(-(acc[i][3] + bias[3])));
            o.x = __expf(8.f * r0 * loga[0]);
            o.y = __expf(8.f * r1 * loga[1]);
            o.z = __expf(8.f * r2 * loga[2]);
            o.w = __expf(8.f * r3 * loga[3]);
            *(float4*)&O[(size_t)(m0 + ty * 8 + i) * DS_ + nbase] = o;
        }
    }
}

// =============================================================================
// Kernel 2: sequential gated-delta recurrence. One CTA/batch, 256 threads.
// Warps 0-3 own rows [0,64), warps 4-7 rows [64,128); lane l of warp w owns
// column (w&3)*32+l as 32 packed fp32-pairs. All hot-loop LDS are warp-uniform
// (free broadcast). Triple-buffered step inputs -> ONE barrier per step with
// no post-barrier race. err computed redundantly per-warp post-barrier.
// y is stored as two half partials, summed in out_kernel.
// =============================================================================
__global__ __launch_bounds__(256, 1) void recurrence_kernel()
{
    const int b    = blockIdx.x;
    const int tid  = threadIdx.x;
    const int w    = tid >> 5;
    const int lane = tid & 31;
    const int half = w >> 2;          // 0: rows [0,64), 1: rows [64,128)
    const int col  = (w & 3) * 32 + lane;
    const int lj   = tid & 127;
    const bool loader_ka = (tid < 128);

    __shared__ __align__(16) float sk[3][DS_];
    __shared__ __align__(16) float sv[3][DS_];
    __shared__ __align__(16) float sq[3][DS_];
    __shared__ __align__(16) float sa[3][DS_];
    __shared__ __align__(16) float sc0[3][DS_];
    __shared__ float spred[2][2][DS_];   // [parity][half][col]
    __shared__ float skp[2][2][DS_];

    u64 h[32];
#pragma unroll
    for (int j = 0; j < 32; j++) h[j] = 0ULL;

    const float* bk = g_k + (size_t)b * S_ * DS_;
    const float* bv = g_v + (size_t)b * S_ * DS_;
    const float* bq = g_q + (size_t)b * S_ * DS_;
    const float* ba = g_a + (size_t)b * S_ * DS_;
    float*       by = (half == 0 ? g_y0 : g_y1) + (size_t)b * S_ * DS_;

    // fill buffer 0
    if (loader_ka) {
        float kk = bk[lj], aa = ba[lj];
        sk[0][lj] = kk; sa[0][lj] = aa; sc0[0][lj] = (1.f - aa) * kk;
    } else {
        sq[0][lj] = bq[lj]; sv[0][lj] = bv[lj];
    }
    __syncthreads();

    int cur = 0;
    for (int step = 0; step < S_; ++step) {
        const int nxt = (cur == 2) ? 0 : cur + 1;
        const int par = step & 1;

        // prefetch next step (global loads issued early)
        float p0 = 0.f, p1 = 0.f;
        if (step + 1 < S_) {
            size_t o = (size_t)(step + 1) * DS_ + lj;
            if (loader_ka) { p0 = bk[o]; p1 = ba[o]; }
            else           { p0 = bq[o]; p1 = bv[o]; }
        }

        // ---- matvecs over this thread's half-column (warp-uniform LDS) ------
        const ulonglong2* q4 = (const ulonglong2*)&sq[cur][half * 64];
        const ulonglong2* k4 = (const ulonglong2*)&sk[cur][half * 64];
        const ulonglong2* a4 = (const ulonglong2*)&sa[cur][half * 64];
        u64 q_r[32];
        u64 p2a = 0, p2b = 0, kp2a = 0, kp2b = 0;
#pragma unroll
        for (int jj = 0; jj < 16; jj++) {
            ulonglong2 qA = q4[jj];
            ulonglong2 kA = k4[jj];
            q_r[2 * jj]     = qA.x;
            q_r[2 * jj + 1] = qA.y;
            p2a  = ffma2(qA.x, h[2 * jj],     p2a);
            kp2a = ffma2(kA.x, h[2 * jj],     kp2a);
            p2b  = ffma2(qA.y, h[2 * jj + 1], p2b);
            kp2b = ffma2(kA.y, h[2 * jj + 1], kp2b);
        }
        float2 pp = up2(fadd2(p2a, p2b));
        float2 kk2 = up2(fadd2(kp2a, kp2b));
        spred[par][half][col] = pp.x + pp.y;
        skp[par][half][col]   = kk2.x + kk2.y;

        // ---- decay h *= a (independent of err; fills issue slots) ----------
#pragma unroll
        for (int jj = 0; jj < 16; jj++) {
            ulonglong2 aA = a4[jj];
            h[2 * jj]     = fmul2(aA.x, h[2 * jj]);
            h[2 * jj + 1] = fmul2(aA.y, h[2 * jj + 1]);
        }

        // stash prefetched step (triple buffer -> no WAR race with readers)
        if (step + 1 < S_) {
            if (loader_ka) {
                sk[nxt][lj] = p0; sa[nxt][lj] = p1; sc0[nxt][lj] = (1.f - p1) * p0;
            } else {
                sq[nxt][lj] = p0; sv[nxt][lj] = p1;
            }
        }
        __syncthreads();   // the ONLY barrier per step

        // ---- every warp redundantly computes full err (4 cols per lane) ----
        float esum;
        {
            float e0, e1, e2, e3;
            {
                float pr = spred[par][0][lane] + spred[par][1][lane];
                float vv = sv[cur][lane];
                float d = vv - pr; e0 = d * d;
            }
            {
                float pr = spred[par][0][lane + 32] + spred[par][1][lane + 32];
                float vv = sv[cur][lane + 32];
                float d = vv - pr; e1 = d * d;
            }
            {
                float pr = spred[par][0][lane + 64] + spred[par][1][lane + 64];
                float vv = sv[cur][lane + 64];
                float d = vv - pr; e2 = d * d;
            }
            {
                float pr = spred[par][0][lane + 96] + spred[par][1][lane + 96];
                float vv = sv[cur][lane + 96];
                float d = vv - pr; e3 = d * d;
            }
            esum = (e0 + e1) + (e2 + e3);
#pragma unroll
            for (int off = 16; off; off >>= 1)
                esum += __shfl_xor_sync(0xffffffffu, esum, off);
        }
        float sur = 1.f / (1.f + __expf(-esum * (1.f / 1.000001f)));

        float kp  = skp[par][0][col] + skp[par][1][col];
        float myv = sv[cur][col];
        float sdv = sur * (myv - kp);
        u64 sdv2 = pk2(sdv, sdv);

        // ---- finish H update and y-half = q . H_new -------------------------
        const ulonglong2* c4 = (const ulonglong2*)&sc0[cur][half * 64];
        u64 y2a = 0, y2b = 0;
#pragma unroll
        for (int jj = 0; jj < 16; jj++) {
            ulonglong2 cA = c4[jj];
            h[2 * jj] = ffma2(cA.x, sdv2, h[2 * jj]);
            y2a = ffma2(q_r[2 * jj], h[2 * jj], y2a);
            h[2 * jj + 1] = ffma2(cA.y, sdv2, h[2 * jj + 1]);
            y2b = ffma2(q_r[2 * jj + 1], h[2 * jj + 1], y2b);
        }
        float2 yy = up2(fadd2(y2a, y2b));
        by[(size_t)step * DS_ + col] = yy.x + yy.y;

        cur = nxt;
    }
}

// =============================================================================
// Kernel 3: sum y halves, fused RMSNorm * norm_weight, then @ W_o^T. FFMA2.
// =============================================================================
__global__ __launch_bounds__(256) void out_kernel(
    const float* __restrict__ Wo, const float* __restrict__ nw,
    float* __restrict__ out)
{
    __shared__ __align__(16) float sY[128][68];   // [k][m]
    __shared__ __align__(16) float sW[16][132];   // [k][n]
    __shared__ float sScale[64];
    __shared__ float snw[128];

    const int tid = threadIdx.x;
    const int tx = tid & 31, ty = tid >> 5;
    const int m0 = blockIdx.x * 64, n0 = blockIdx.y * 128;

    if (tid < 128) snw[tid] = nw[tid];

#pragma unroll
    for (int it = 0; it < 8; it++) {
        int idx = tid + it * 256;
        int row = idx >> 5;
        int k4  = (idx & 31) * 4;
        float4 v0 = *(const float4*)&g_y0[(size_t)(m0 + row) * DS_ + k4];
        float4 v1 = *(const float4*)&g_y1[(size_t)(m0 + row) * DS_ + k4];
        sY[k4 + 0][row] = v0.x + v1.x; sY[k4 + 1][row] = v0.y + v1.y;
        sY[k4 + 2][row] = v0.z + v1.z; sY[k4 + 3][row] = v0.w + v1.w;
    }
    __syncthreads();

    {
        int row = tid >> 2, part = tid & 3;
        float ss = 0.f;
#pragma unroll
        for (int kkk = 0; kkk < 32; kkk++) {
            float v = sY[part * 32 + kkk][row];
            ss = fmaf(v, v, ss);
        }
        ss += __shfl_xor_sync(0xffffffffu, ss, 1);
        ss += __shfl_xor_sync(0xffffffffu, ss, 2);
        if (part == 0) sScale[row] = rsqrtf(ss * (1.f / 128.f) + 1e-6f);
    }
    __syncthreads();

    for (int idx = tid; idx < 128 * 64; idx += 256) {
        int k = idx >> 6, m = idx & 63;
        sY[k][m] *= sScale[m];
    }

    u64 acc2[8][2];
#pragma unroll
    for (int i = 0; i < 8; i++) { acc2[i][0] = 0ULL; acc2[i][1] = 0ULL; }

    for (int kc = 0; kc < DS_; kc += 16) {
        int n0a = tid >> 2, k0a = (tid & 3) * 4;
        float4 w0 = *(const float4*)&Wo[(size_t)(n0 + n0a) * DS_ + kc + k0a];
        int idx2 = tid + 256;
        int n0b = idx2 >> 2, k0b = (idx2 & 3) * 4;
        float4 w1 = *(const float4*)&Wo[(size_t)(n0 + n0b) * DS_ + kc + k0b];

        __syncthreads();
        sW[k0a + 0][n0a] = w0.x * snw[kc + k0a + 0];
        sW[k0a + 1][n0a] = w0.y * snw[kc + k0a + 1];
        sW[k0a + 2][n0a] = w0.z * snw[kc + k0a + 2];
        sW[k0a + 3][n0a] = w0.w * snw[kc + k0a + 3];
        sW[k0b + 0][n0b] = w1.x * snw[kc + k0b + 0];
        sW[k0b + 1][n0b] = w1.y * snw[kc + k0b + 1];
        sW[k0b + 2][n0b] = w1.z * snw[kc + k0b + 2];
        sW[k0b + 3][n0b] = w1.w * snw[kc + k0b + 3];
        __syncthreads();

#pragma unroll
        for (int k = 0; k < 16; k++) {
            ulonglong2 b4 = *(const ulonglong2*)&sW[k][tx * 4];
            float a_[8];
#pragma unroll
            for (int i = 0; i < 8; i++) a_[i] = sY[kc + k][ty * 8 + i];
#pragma unroll
            for (int i = 0; i < 8; i++) {
                u64 a2 = pk2(a_[i], a_[i]);
                acc2[i][0] = ffma2(a2, b4.x, acc2[i][0]);
                acc2[i][1] = ffma2(a2, b4.y, acc2[i][1]);
            }
        }
    }

#pragma unroll
    for (int i = 0; i < 8; i++) {
        float2 lo = up2(acc2[i][0]);
        float2 hi = up2(acc2[i][1]);
        float4 o = make_float4(lo.x, lo.y, hi.x, hi.y);
        *(float4*)&out[(size_t)(m0 + ty * 8 + i) * D_ + n0 + tx * 4] = o;
    }
}

// =============================================================================
extern "C" void kernel_launch(void* const* d_in, const int* in_sizes, int n_in,
                              void* d_out, int out_size)
{
    const float* x   = (const float*)d_in[0];
    const float* Wk  = (const float*)d_in[1];
    const float* Wv  = (const float*)d_in[2];
    const float* Wq  = (const float*)d_in[3];
    const float* Waw = (const float*)d_in[4];
    const float* Wab = (const float*)d_in[5];
    const float* lam = (const float*)d_in[6];
    const float* Wo  = (const float*)d_in[7];
    const float* nw  = (const float*)d_in[8];
    float* out = (float*)d_out;

    dim3 g1(MROWS / 64, 4);
    proj_kernel<<<g1, 256>>>(x, Wk, Wv, Wq, Waw, Wab, lam);

    recurrence_kernel<<<B_, 256>>>();

    dim3 g3(MROWS / 64, D_ / 128);
    out_kernel<<<g3, 256>>>(Wo, nw, out);
}